// round 1
// baseline (speedup 1.0000x reference)
#include <cuda_runtime.h>
#include <math.h>

#define B  64
#define T  512
#define IN 512
#define H  1024
#define G3 (3*H)
#define BT (B*T)

// ---------------- scratch (device globals; no runtime allocation) ----------------
__device__ float g_xg[(size_t)BT * G3];   // 32768 x 3072 input-side gate pre-activations (~402 MB)
__device__ float g_h[2][B * H];           // double-buffered hidden state
__device__ unsigned g_bar_count;
__device__ unsigned g_bar_gen;

// ---------------- grid barrier (all CTAs co-resident by construction) ----------------
__device__ __forceinline__ void grid_sync(int ncta) {
    __syncthreads();
    if (threadIdx.x == 0) {
        __threadfence();                                   // flush h writes
        unsigned gen = atomicAdd(&g_bar_gen, 0u);          // read BEFORE arriving
        if (atomicAdd(&g_bar_count, 1u) == (unsigned)(ncta - 1)) {
            g_bar_count = 0u;
            __threadfence();
            atomicAdd(&g_bar_gen, 1u);                     // release
        } else {
            while (atomicAdd(&g_bar_gen, 0u) == gen) { __nanosleep(64); }
        }
    }
    __syncthreads();
}

// ---------------- zero initial hidden state ----------------
__global__ void zero_h_kernel() {
    int i = blockIdx.x * blockDim.x + threadIdx.x;
    if (i < B * H) g_h[0][i] = 0.0f;
}

// ---------------- phase 1: xg = x @ [Wir;Wii;Win]^T + b  (fused over 3 gates) ----------------
#define BM 128
#define BN 64
#define BK 16

__global__ __launch_bounds__(256) void xproj_kernel(
    const float* __restrict__ x,
    const float* __restrict__ Wir, const float* __restrict__ Wii, const float* __restrict__ Win,
    const float* __restrict__ bir, const float* __restrict__ bii, const float* __restrict__ bin)
{
    __shared__ float As[BK][BM];
    __shared__ float Bs[BK][BN];

    int tid = threadIdx.x;
    int bm  = blockIdx.x;          // 0..255  (M tiles)
    int bn  = blockIdx.y;          // 0..47   (N tiles across 3 gates)
    int gate = bn >> 4;            // 16 N-tiles of 64 per gate (H=1024)
    const float* W    = (gate == 0) ? Wir : (gate == 1) ? Wii : Win;
    const float* bias = (gate == 0) ? bir : (gate == 1) ? bii : bin;
    int n0 = (bn & 15) * BN;       // column offset within this gate
    int m0 = bm * BM;

    int trow = tid >> 4;           // 0..15 -> 8 M rows each
    int tcol = tid & 15;           // 0..15 -> 4 N cols each

    float acc[8][4];
    #pragma unroll
    for (int u = 0; u < 8; u++)
        #pragma unroll
        for (int v = 0; v < 4; v++) acc[u][v] = 0.0f;

    for (int k0 = 0; k0 < IN; k0 += BK) {
        // load A tile (128x16), store transposed As[k][m]
        #pragma unroll
        for (int i = 0; i < 2; i++) {
            int f   = tid + i * 256;
            int row = f >> 2;
            int c4  = (f & 3) * 4;
            float4 a = *(const float4*)(x + (size_t)(m0 + row) * IN + k0 + c4);
            As[c4 + 0][row] = a.x; As[c4 + 1][row] = a.y;
            As[c4 + 2][row] = a.z; As[c4 + 3][row] = a.w;
        }
        // load B tile (64x16) from W rows n0..n0+63, store transposed Bs[k][n]
        {
            int row = tid >> 2;
            int c4  = (tid & 3) * 4;
            float4 b = *(const float4*)(W + (size_t)(n0 + row) * IN + k0 + c4);
            Bs[c4 + 0][row] = b.x; Bs[c4 + 1][row] = b.y;
            Bs[c4 + 2][row] = b.z; Bs[c4 + 3][row] = b.w;
        }
        __syncthreads();

        #pragma unroll
        for (int kk = 0; kk < BK; kk++) {
            float4 a0 = *(float4*)&As[kk][trow * 8];
            float4 a1 = *(float4*)&As[kk][trow * 8 + 4];
            float4 bb = *(float4*)&Bs[kk][tcol * 4];
            float a[8] = {a0.x, a0.y, a0.z, a0.w, a1.x, a1.y, a1.z, a1.w};
            float bv[4] = {bb.x, bb.y, bb.z, bb.w};
            #pragma unroll
            for (int u = 0; u < 8; u++)
                #pragma unroll
                for (int v = 0; v < 4; v++)
                    acc[u][v] += a[u] * bv[v];
        }
        __syncthreads();
    }

    // epilogue: add bias, store to g_xg[m][gate*H + n]
    int jbase = gate * H + n0 + tcol * 4;
    float4 bv4 = *(const float4*)(bias + n0 + tcol * 4);
    float bb[4] = {bv4.x, bv4.y, bv4.z, bv4.w};
    #pragma unroll
    for (int u = 0; u < 8; u++) {
        int m = m0 + trow * 8 + u;
        float4 o;
        o.x = acc[u][0] + bb[0];
        o.y = acc[u][1] + bb[1];
        o.z = acc[u][2] + bb[2];
        o.w = acc[u][3] + bb[3];
        *(float4*)(g_xg + (size_t)m * G3 + jbase) = o;
    }
}

// ---------------- phase 2: persistent GRU recurrence ----------------
#define NCTA 128
#define HS   8          // hidden cols per CTA (H / NCTA)
#define KT   128        // K tile
#define HSP  (KT + 4)   // padded smem stride

__device__ __forceinline__ float sigmoidf_(float v) { return 1.0f / (1.0f + expf(-v)); }

__global__ __launch_bounds__(256) void gru_kernel(
    const float* __restrict__ Whr, const float* __restrict__ Whi, const float* __restrict__ Whn,
    float* __restrict__ out, int write_last)
{
    __shared__ float Hs[B][HSP];          // 64 x 132 fp32  (33.8 KB)
    __shared__ float Ws[3][HS][HSP];      // 3 x 8 x 132    (12.7 KB)

    int tid = threadIdx.x;
    int c   = blockIdx.x;                 // 0..127
    int jh  = tid & 7;                    // local hidden col
    int bg  = tid >> 3;                   // 0..31
    int b0  = bg, b1 = bg + 32;
    int jg  = c * HS + jh;                // global hidden col

    const float* Wg[3] = {Whr, Whi, Whn};

    for (int t = 0; t < T; t++) {
        int par = t & 1;
        const float* hin  = g_h[par];
        float*       hout = g_h[par ^ 1];

        float ar0 = 0.f, ai0 = 0.f, an0 = 0.f;
        float ar1 = 0.f, ai1 = 0.f, an1 = 0.f;

        for (int k0 = 0; k0 < H; k0 += KT) {
            // load h tile: 64 x 128 (2048 float4, 8 per thread)
            #pragma unroll
            for (int i = 0; i < 8; i++) {
                int f    = tid + i * 256;
                int b    = f >> 5;
                int kcol = (f & 31) * 4;
                float4 v = *(const float4*)(hin + (size_t)b * H + k0 + kcol);
                *(float4*)&Hs[b][kcol] = v;
            }
            // load weight tile: 3 gates x 8 rows x 128
            #pragma unroll
            for (int g = 0; g < 3; g++) {
                int row  = tid >> 5;
                int kcol = (tid & 31) * 4;
                float4 v = *(const float4*)(Wg[g] + (size_t)(c * HS + row) * H + k0 + kcol);
                *(float4*)&Ws[g][row][kcol] = v;
            }
            __syncthreads();

            #pragma unroll 8
            for (int kk = 0; kk < KT; kk += 4) {
                float4 h0 = *(float4*)&Hs[b0][kk];
                float4 h1 = *(float4*)&Hs[b1][kk];
                float4 wr = *(float4*)&Ws[0][jh][kk];
                float4 wi = *(float4*)&Ws[1][jh][kk];
                float4 wn = *(float4*)&Ws[2][jh][kk];
                ar0 += h0.x * wr.x; ar0 += h0.y * wr.y; ar0 += h0.z * wr.z; ar0 += h0.w * wr.w;
                ai0 += h0.x * wi.x; ai0 += h0.y * wi.y; ai0 += h0.z * wi.z; ai0 += h0.w * wi.w;
                an0 += h0.x * wn.x; an0 += h0.y * wn.y; an0 += h0.z * wn.z; an0 += h0.w * wn.w;
                ar1 += h1.x * wr.x; ar1 += h1.y * wr.y; ar1 += h1.z * wr.z; ar1 += h1.w * wr.w;
                ai1 += h1.x * wi.x; ai1 += h1.y * wi.y; ai1 += h1.z * wi.z; ai1 += h1.w * wi.w;
                an1 += h1.x * wn.x; an1 += h1.y * wn.y; an1 += h1.z * wn.z; an1 += h1.w * wn.w;
            }
            __syncthreads();
        }

        // epilogue: gates + state update for (b0, jg) and (b1, jg)
        {
            size_t row0 = (size_t)(b0 * T + t) * G3;
            float xr = g_xg[row0 + jg];
            float xi = g_xg[row0 + H + jg];
            float xn = g_xg[row0 + 2 * H + jg];
            float r  = sigmoidf_(xr + ar0);
            float z  = sigmoidf_(xi + ai0);
            float hp = hin[(size_t)b0 * H + jg];
            float n  = tanhf(xn + r * an0);
            float hn = (1.0f - z) * n + z * hp;
            hout[(size_t)b0 * H + jg] = hn;
            out[(size_t)(b0 * T + t) * H + jg] = hn;
            if (write_last && t == T - 1) out[(size_t)BT * H + (size_t)b0 * H + jg] = hn;
        }
        {
            size_t row1 = (size_t)(b1 * T + t) * G3;
            float xr = g_xg[row1 + jg];
            float xi = g_xg[row1 + H + jg];
            float xn = g_xg[row1 + 2 * H + jg];
            float r  = sigmoidf_(xr + ar1);
            float z  = sigmoidf_(xi + ai1);
            float hp = hin[(size_t)b1 * H + jg];
            float n  = tanhf(xn + r * an1);
            float hn = (1.0f - z) * n + z * hp;
            hout[(size_t)b1 * H + jg] = hn;
            out[(size_t)(b1 * T + t) * H + jg] = hn;
            if (write_last && t == T - 1) out[(size_t)BT * H + (size_t)b1 * H + jg] = hn;
        }

        grid_sync(NCTA);
    }
}

// ---------------- launch ----------------
extern "C" void kernel_launch(void* const* d_in, const int* in_sizes, int n_in,
                              void* d_out, int out_size) {
    const float* x   = (const float*)d_in[0];
    const float* Wir = (const float*)d_in[1];
    const float* Wii = (const float*)d_in[2];
    const float* Win = (const float*)d_in[3];
    const float* bir = (const float*)d_in[4];
    const float* bii = (const float*)d_in[5];
    const float* bin = (const float*)d_in[6];
    const float* Whr = (const float*)d_in[7];
    const float* Whi = (const float*)d_in[8];
    const float* Whn = (const float*)d_in[9];
    float* out = (float*)d_out;

    int write_last = (out_size >= BT * H + B * H) ? 1 : 0;

    zero_h_kernel<<<(B * H + 255) / 256, 256>>>();

    dim3 g1(BT / BM, G3 / BN);   // 256 x 48
    xproj_kernel<<<g1, 256>>>(x, Wir, Wii, Win, bir, bii, bin);

    gru_kernel<<<NCTA, 256>>>(Whr, Whi, Whn, out, write_last);
}

// round 2
// speedup vs baseline: 1.0031x; 1.0031x over previous
#include <cuda_runtime.h>
#include <math.h>

#define B  64
#define T  512
#define IN 512
#define H  1024
#define G3 (3*H)
#define BT (B*T)

// ---------------- scratch (device globals; no runtime allocation) ----------------
__device__ float g_xg[(size_t)BT * G3];   // 32768 x 3072 input-side gate pre-activations (~402 MB)
__device__ float g_h[2][B * H];           // double-buffered hidden state
__device__ unsigned g_bar_count;
__device__ unsigned g_bar_gen;

// ---------------- grid barrier (all CTAs co-resident by construction) ----------------
__device__ __forceinline__ void grid_sync(int ncta) {
    __syncthreads();
    if (threadIdx.x == 0) {
        __threadfence();                                   // flush h writes
        unsigned gen = atomicAdd(&g_bar_gen, 0u);          // read BEFORE arriving
        if (atomicAdd(&g_bar_count, 1u) == (unsigned)(ncta - 1)) {
            g_bar_count = 0u;
            __threadfence();
            atomicAdd(&g_bar_gen, 1u);                     // release
        } else {
            while (atomicAdd(&g_bar_gen, 0u) == gen) { __nanosleep(64); }
        }
    }
    __syncthreads();
}

// ---------------- zero initial hidden state ----------------
__global__ void zero_h_kernel() {
    int i = blockIdx.x * blockDim.x + threadIdx.x;
    if (i < B * H) g_h[0][i] = 0.0f;
}

// ---------------- phase 1: xg = x @ [Wir;Wii;Win]^T + b  (fused over 3 gates) ----------------
#define BM 128
#define BN 64
#define BK 16

__global__ __launch_bounds__(256) void xproj_kernel(
    const float* __restrict__ x,
    const float* __restrict__ Wir, const float* __restrict__ Wii, const float* __restrict__ Win,
    const float* __restrict__ bir, const float* __restrict__ bii, const float* __restrict__ bin)
{
    __shared__ float As[BK][BM];
    __shared__ float Bs[BK][BN];

    int tid = threadIdx.x;
    int bm  = blockIdx.x;          // 0..255  (M tiles)
    int bn  = blockIdx.y;          // 0..47   (N tiles across 3 gates)
    int gate = bn >> 4;            // 16 N-tiles of 64 per gate (H=1024)
    const float* W    = (gate == 0) ? Wir : (gate == 1) ? Wii : Win;
    const float* bias = (gate == 0) ? bir : (gate == 1) ? bii : bin;
    int n0 = (bn & 15) * BN;       // column offset within this gate
    int m0 = bm * BM;

    int trow = tid >> 4;           // 0..15 -> 8 M rows each
    int tcol = tid & 15;           // 0..15 -> 4 N cols each

    float acc[8][4];
    #pragma unroll
    for (int u = 0; u < 8; u++)
        #pragma unroll
        for (int v = 0; v < 4; v++) acc[u][v] = 0.0f;

    for (int k0 = 0; k0 < IN; k0 += BK) {
        // load A tile (128x16), store transposed As[k][m]
        #pragma unroll
        for (int i = 0; i < 2; i++) {
            int f   = tid + i * 256;
            int row = f >> 2;
            int c4  = (f & 3) * 4;
            float4 a = *(const float4*)(x + (size_t)(m0 + row) * IN + k0 + c4);
            As[c4 + 0][row] = a.x; As[c4 + 1][row] = a.y;
            As[c4 + 2][row] = a.z; As[c4 + 3][row] = a.w;
        }
        // load B tile (64x16) from W rows n0..n0+63, store transposed Bs[k][n]
        {
            int row = tid >> 2;
            int c4  = (tid & 3) * 4;
            float4 b = *(const float4*)(W + (size_t)(n0 + row) * IN + k0 + c4);
            Bs[c4 + 0][row] = b.x; Bs[c4 + 1][row] = b.y;
            Bs[c4 + 2][row] = b.z; Bs[c4 + 3][row] = b.w;
        }
        __syncthreads();

        #pragma unroll
        for (int kk = 0; kk < BK; kk++) {
            float4 a0 = *(float4*)&As[kk][trow * 8];
            float4 a1 = *(float4*)&As[kk][trow * 8 + 4];
            float4 bb = *(float4*)&Bs[kk][tcol * 4];
            float a[8] = {a0.x, a0.y, a0.z, a0.w, a1.x, a1.y, a1.z, a1.w};
            float bv[4] = {bb.x, bb.y, bb.z, bb.w};
            #pragma unroll
            for (int u = 0; u < 8; u++)
                #pragma unroll
                for (int v = 0; v < 4; v++)
                    acc[u][v] += a[u] * bv[v];
        }
        __syncthreads();
    }

    // epilogue: add bias, store to g_xg[m][gate*H + n]
    int jbase = gate * H + n0 + tcol * 4;
    float4 bv4 = *(const float4*)(bias + n0 + tcol * 4);
    float bb[4] = {bv4.x, bv4.y, bv4.z, bv4.w};
    #pragma unroll
    for (int u = 0; u < 8; u++) {
        int m = m0 + trow * 8 + u;
        float4 o;
        o.x = acc[u][0] + bb[0];
        o.y = acc[u][1] + bb[1];
        o.z = acc[u][2] + bb[2];
        o.w = acc[u][3] + bb[3];
        *(float4*)(g_xg + (size_t)m * G3 + jbase) = o;
    }
}

// ---------------- phase 2: persistent GRU recurrence ----------------
#define NCTA 128
#define HS   8          // hidden cols per CTA (H / NCTA)
#define KT   128        // K tile
#define HSP  (KT + 4)   // padded smem stride

__device__ __forceinline__ float sigmoidf_(float v) { return 1.0f / (1.0f + expf(-v)); }

__global__ __launch_bounds__(256) void gru_kernel(
    const float* __restrict__ Whr, const float* __restrict__ Whi, const float* __restrict__ Whn,
    float* __restrict__ out, int write_last)
{
    __shared__ float Hs[B][HSP];          // 64 x 132 fp32  (33.8 KB)
    __shared__ float Ws[3][HS][HSP];      // 3 x 8 x 132    (12.7 KB)

    int tid = threadIdx.x;
    int c   = blockIdx.x;                 // 0..127
    int jh  = tid & 7;                    // local hidden col
    int bg  = tid >> 3;                   // 0..31
    int b0  = bg, b1 = bg + 32;
    int jg  = c * HS + jh;                // global hidden col

    const float* Wg[3] = {Whr, Whi, Whn};

    for (int t = 0; t < T; t++) {
        int par = t & 1;
        const float* hin  = g_h[par];
        float*       hout = g_h[par ^ 1];

        float ar0 = 0.f, ai0 = 0.f, an0 = 0.f;
        float ar1 = 0.f, ai1 = 0.f, an1 = 0.f;

        for (int k0 = 0; k0 < H; k0 += KT) {
            // load h tile: 64 x 128 (2048 float4, 8 per thread)
            #pragma unroll
            for (int i = 0; i < 8; i++) {
                int f    = tid + i * 256;
                int b    = f >> 5;
                int kcol = (f & 31) * 4;
                float4 v = *(const float4*)(hin + (size_t)b * H + k0 + kcol);
                *(float4*)&Hs[b][kcol] = v;
            }
            // load weight tile: 3 gates x 8 rows x 128
            #pragma unroll
            for (int g = 0; g < 3; g++) {
                int row  = tid >> 5;
                int kcol = (tid & 31) * 4;
                float4 v = *(const float4*)(Wg[g] + (size_t)(c * HS + row) * H + k0 + kcol);
                *(float4*)&Ws[g][row][kcol] = v;
            }
            __syncthreads();

            #pragma unroll 8
            for (int kk = 0; kk < KT; kk += 4) {
                float4 h0 = *(float4*)&Hs[b0][kk];
                float4 h1 = *(float4*)&Hs[b1][kk];
                float4 wr = *(float4*)&Ws[0][jh][kk];
                float4 wi = *(float4*)&Ws[1][jh][kk];
                float4 wn = *(float4*)&Ws[2][jh][kk];
                ar0 += h0.x * wr.x; ar0 += h0.y * wr.y; ar0 += h0.z * wr.z; ar0 += h0.w * wr.w;
                ai0 += h0.x * wi.x; ai0 += h0.y * wi.y; ai0 += h0.z * wi.z; ai0 += h0.w * wi.w;
                an0 += h0.x * wn.x; an0 += h0.y * wn.y; an0 += h0.z * wn.z; an0 += h0.w * wn.w;
                ar1 += h1.x * wr.x; ar1 += h1.y * wr.y; ar1 += h1.z * wr.z; ar1 += h1.w * wr.w;
                ai1 += h1.x * wi.x; ai1 += h1.y * wi.y; ai1 += h1.z * wi.z; ai1 += h1.w * wi.w;
                an1 += h1.x * wn.x; an1 += h1.y * wn.y; an1 += h1.z * wn.z; an1 += h1.w * wn.w;
            }
            __syncthreads();
        }

        // epilogue: gates + state update for (b0, jg) and (b1, jg)
        {
            size_t row0 = (size_t)(b0 * T + t) * G3;
            float xr = g_xg[row0 + jg];
            float xi = g_xg[row0 + H + jg];
            float xn = g_xg[row0 + 2 * H + jg];
            float r  = sigmoidf_(xr + ar0);
            float z  = sigmoidf_(xi + ai0);
            float hp = hin[(size_t)b0 * H + jg];
            float n  = tanhf(xn + r * an0);
            float hn = (1.0f - z) * n + z * hp;
            hout[(size_t)b0 * H + jg] = hn;
            out[(size_t)(b0 * T + t) * H + jg] = hn;
            if (write_last && t == T - 1) out[(size_t)BT * H + (size_t)b0 * H + jg] = hn;
        }
        {
            size_t row1 = (size_t)(b1 * T + t) * G3;
            float xr = g_xg[row1 + jg];
            float xi = g_xg[row1 + H + jg];
            float xn = g_xg[row1 + 2 * H + jg];
            float r  = sigmoidf_(xr + ar1);
            float z  = sigmoidf_(xi + ai1);
            float hp = hin[(size_t)b1 * H + jg];
            float n  = tanhf(xn + r * an1);
            float hn = (1.0f - z) * n + z * hp;
            hout[(size_t)b1 * H + jg] = hn;
            out[(size_t)(b1 * T + t) * H + jg] = hn;
            if (write_last && t == T - 1) out[(size_t)BT * H + (size_t)b1 * H + jg] = hn;
        }

        grid_sync(NCTA);
    }
}

// ---------------- launch ----------------
extern "C" void kernel_launch(void* const* d_in, const int* in_sizes, int n_in,
                              void* d_out, int out_size) {
    const float* x   = (const float*)d_in[0];
    const float* Wir = (const float*)d_in[1];
    const float* Wii = (const float*)d_in[2];
    const float* Win = (const float*)d_in[3];
    const float* bir = (const float*)d_in[4];
    const float* bii = (const float*)d_in[5];
    const float* bin = (const float*)d_in[6];
    const float* Whr = (const float*)d_in[7];
    const float* Whi = (const float*)d_in[8];
    const float* Whn = (const float*)d_in[9];
    float* out = (float*)d_out;

    int write_last = (out_size >= BT * H + B * H) ? 1 : 0;

    zero_h_kernel<<<(B * H + 255) / 256, 256>>>();

    dim3 g1(BT / BM, G3 / BN);   // 256 x 48
    xproj_kernel<<<g1, 256>>>(x, Wir, Wii, Win, bir, bii, bin);

    gru_kernel<<<NCTA, 256>>>(Whr, Whi, Whn, out, write_last);
}

// round 7
// speedup vs baseline: 1.8160x; 1.8103x over previous
#include <cuda_runtime.h>
#include <cuda_bf16.h>
#include <math.h>
#include <stdint.h>

#define Bz 64
#define Tz 512
#define INz 512
#define Hz 1024
#define G3z 3072
#define BTz 32768

__device__ __align__(16) float g_xg[(size_t)BTz * G3z];
__device__ __align__(16) __nv_bfloat16 g_xhi[(size_t)BTz * INz];
__device__ __align__(16) __nv_bfloat16 g_xlo[(size_t)BTz * INz];
__device__ __align__(16) __nv_bfloat16 g_whi[G3z * INz];
__device__ __align__(16) __nv_bfloat16 g_wlo[G3z * INz];
__device__ __align__(16) float g_bias[G3z];
__device__ __align__(16) __nv_bfloat16 g_hhi[2][Bz * Hz];
__device__ __align__(16) __nv_bfloat16 g_hlo[2][Bz * Hz];
__device__ unsigned g_bc, g_bg;

// ---------------- helpers ----------------
__device__ __forceinline__ uint32_t s2u(const void* p) {
    uint32_t a;
    asm("{ .reg .u64 t; cvta.to.shared.u64 t, %1; cvt.u32.u64 %0, t; }" : "=r"(a) : "l"(p));
    return a;
}
#define SWZ(o) ((uint32_t)(o) ^ (((uint32_t)(o) >> 3) & 0x70u))

#define LDSM4(r, a) asm volatile("ldmatrix.sync.aligned.m8n8.x4.shared.b16 {%0,%1,%2,%3}, [%4];" \
    : "=r"((r)[0]), "=r"((r)[1]), "=r"((r)[2]), "=r"((r)[3]) : "r"(a))
#define LDSM2(r, a) asm volatile("ldmatrix.sync.aligned.m8n8.x2.shared.b16 {%0,%1}, [%2];" \
    : "=r"((r)[0]), "=r"((r)[1]) : "r"(a))
#define MMA(d, a, b) asm volatile( \
    "mma.sync.aligned.m16n8k16.row.col.f32.bf16.bf16.f32 " \
    "{%0,%1,%2,%3}, {%4,%5,%6,%7}, {%8,%9}, {%0,%1,%2,%3};" \
    : "+f"((d)[0]), "+f"((d)[1]), "+f"((d)[2]), "+f"((d)[3]) \
    : "r"((a)[0]), "r"((a)[1]), "r"((a)[2]), "r"((a)[3]), "r"((b)[0]), "r"((b)[1]))

__device__ __forceinline__ void cvt8(float4 v0, float4 v1, uint4& hi, uint4& lo) {
    float f[8] = {v0.x, v0.y, v0.z, v0.w, v1.x, v1.y, v1.z, v1.w};
    uint32_t h[4], l[4];
    #pragma unroll
    for (int i = 0; i < 4; i++) {
        __nv_bfloat16 a = __float2bfloat16(f[2*i]), b = __float2bfloat16(f[2*i+1]);
        __nv_bfloat16 al = __float2bfloat16(f[2*i] - __bfloat162float(a));
        __nv_bfloat16 bl = __float2bfloat16(f[2*i+1] - __bfloat162float(b));
        __nv_bfloat162 hp = __halves2bfloat162(a, b), lp = __halves2bfloat162(al, bl);
        h[i] = *reinterpret_cast<uint32_t*>(&hp);
        l[i] = *reinterpret_cast<uint32_t*>(&lp);
    }
    hi = make_uint4(h[0], h[1], h[2], h[3]);
    lo = make_uint4(l[0], l[1], l[2], l[3]);
}

__device__ __forceinline__ void grid_sync_(int n) {
    __threadfence();
    __syncthreads();
    if (threadIdx.x == 0) {
        unsigned gen = atomicAdd(&g_bg, 0u);
        if (atomicAdd(&g_bc, 1u) == (unsigned)(n - 1)) {
            g_bc = 0u;
            __threadfence();
            atomicAdd(&g_bg, 1u);
        } else {
            while (atomicAdd(&g_bg, 0u) == gen) { __nanosleep(64); }
        }
    }
    __syncthreads();
}

// ---------------- one-time converts ----------------
__global__ void cvt_x(const float* __restrict__ x) {
    size_t u = (size_t)blockIdx.x * 256 + threadIdx.x;   // 16B unit (8 elems)
    if (u < (size_t)BTz * INz / 8) {
        float4 a = *(const float4*)(x + u * 8);
        float4 b = *(const float4*)(x + u * 8 + 4);
        uint4 hi, lo; cvt8(a, b, hi, lo);
        *(uint4*)(g_xhi + u * 8) = hi;
        *(uint4*)(g_xlo + u * 8) = lo;
    }
}

__global__ void cvt_w(const float* __restrict__ Wir, const float* __restrict__ Wii, const float* __restrict__ Win,
                      const float* __restrict__ bir, const float* __restrict__ bii, const float* __restrict__ bin) {
    int u = blockIdx.x * 256 + threadIdx.x;
    if (u < G3z * INz / 8) {
        int row = u >> 6, un = u & 63;
        int gate = row >> 10, r = row & 1023;
        const float* W = (gate == 0) ? Wir : (gate == 1) ? Wii : Win;
        const float* s = W + (size_t)r * INz + un * 8;
        float4 a = *(const float4*)s, b = *(const float4*)(s + 4);
        uint4 hi, lo; cvt8(a, b, hi, lo);
        *(uint4*)(g_whi + (size_t)u * 8) = hi;
        *(uint4*)(g_wlo + (size_t)u * 8) = lo;
    }
    if (u < G3z) {
        int gate = u >> 10;
        const float* bb = (gate == 0) ? bir : (gate == 1) ? bii : bin;
        g_bias[u] = bb[u & 1023];
    }
}

__global__ void init_h() {
    int i = blockIdx.x * blockDim.x + threadIdx.x;
    if (i < Bz * Hz) {
        g_hhi[0][i] = __float2bfloat16(0.0f);
        g_hlo[0][i] = __float2bfloat16(0.0f);
    }
}

// ---------------- phase 1: xg = x @ Wi^T + b (mma.sync bf16 hi/lo) ----------------
// smem: AH 0 (16K) | AL 16384 | BH 32768 (8K) | BL 40960 | total 49152
__global__ __launch_bounds__(256, 2) void xproj(void) {
    extern __shared__ __align__(16) char sm[];
    uint32_t sb = s2u(sm);
    int tid = threadIdx.x, lane = tid & 31, wid = tid >> 5;
    int m0 = blockIdx.x * 128;
    int n0 = blockIdx.y * 64;
    int wm = wid >> 1, wn = wid & 1;

    float acc[2][4][4];
    #pragma unroll
    for (int i = 0; i < 2; i++)
        #pragma unroll
        for (int j = 0; j < 4; j++)
            #pragma unroll
            for (int k = 0; k < 4; k++) acc[i][j][k] = 0.0f;

    for (int kc = 0; kc < 8; kc++) {
        int k0 = kc * 64;
        #pragma unroll
        for (int i = 0; i < 4; i++) {                     // A: 1024 units
            int u = tid + i * 256;
            int row = u >> 3, un = u & 7;
            size_t g = (size_t)(m0 + row) * INz + k0 + un * 8;
            uint32_t d = SWZ(row * 128 + un * 16);
            *(uint4*)(sm + d)          = *(const uint4*)(g_xhi + g);
            *(uint4*)(sm + 16384 + d)  = *(const uint4*)(g_xlo + g);
        }
        #pragma unroll
        for (int i = 0; i < 2; i++) {                     // B: 512 units
            int u = tid + i * 256;
            int row = u >> 3, un = u & 7;
            size_t g = (size_t)(n0 + row) * INz + k0 + un * 8;
            uint32_t d = SWZ(row * 128 + un * 16);
            *(uint4*)(sm + 32768 + d)  = *(const uint4*)(g_whi + g);
            *(uint4*)(sm + 40960 + d)  = *(const uint4*)(g_wlo + g);
        }
        __syncthreads();

        #pragma unroll
        for (int ks = 0; ks < 4; ks++) {
            uint32_t ah0[4], ah1[4], al0[4], al1[4], bh[8], bl[8];
            int arow = wm * 32 + (lane & 7) + (lane & 8);
            int aku  = ks * 2 + (lane >> 4);
            uint32_t o0 = SWZ(arow * 128 + aku * 16);
            uint32_t o1 = SWZ((arow + 16) * 128 + aku * 16);
            LDSM4(ah0, sb + o0);          LDSM4(ah1, sb + o1);
            LDSM4(al0, sb + 16384 + o0);  LDSM4(al1, sb + 16384 + o1);
            int brow = wn * 32 + (lane & 7) + ((lane >> 4) & 1) * 8;
            int bku  = ks * 2 + ((lane >> 3) & 1);
            uint32_t p0 = SWZ(brow * 128 + bku * 16);
            uint32_t p1 = SWZ((brow + 16) * 128 + bku * 16);
            LDSM4(bh,     sb + 32768 + p0);  LDSM4(bh + 4, sb + 32768 + p1);
            LDSM4(bl,     sb + 40960 + p0);  LDSM4(bl + 4, sb + 40960 + p1);
            #pragma unroll
            for (int nt = 0; nt < 4; nt++) {
                MMA(acc[0][nt], ah0, bh + nt * 2);
                MMA(acc[1][nt], ah1, bh + nt * 2);
                MMA(acc[0][nt], ah0, bl + nt * 2);
                MMA(acc[1][nt], ah1, bl + nt * 2);
                MMA(acc[0][nt], al0, bh + nt * 2);
                MMA(acc[1][nt], al1, bh + nt * 2);
            }
        }
        __syncthreads();
    }

    #pragma unroll
    for (int mt = 0; mt < 2; mt++)
        #pragma unroll
        for (int nt = 0; nt < 4; nt++) {
            int m = m0 + wm * 32 + mt * 16 + (lane >> 2);
            int n = n0 + wn * 32 + nt * 8 + 2 * (lane & 3);
            float b0 = __ldg(g_bias + n), b1 = __ldg(g_bias + n + 1);
            *(float2*)(g_xg + (size_t)m * G3z + n)       = make_float2(acc[mt][nt][0] + b0, acc[mt][nt][1] + b1);
            *(float2*)(g_xg + (size_t)(m + 8) * G3z + n) = make_float2(acc[mt][nt][2] + b0, acc[mt][nt][3] + b1);
        }
}

// ---------------- phase 2: persistent recurrence (mma.sync bf16 hi/lo) ----------------
// smem: WH 0 (64K) | WL 65536 | A0H 131072 | A0L 147456 | A1H 163840 | A1L 180224
//       Sacc 196608 (64*33*4=8448) | hown 205056 (2048) | total 207104
#define NCTA 128
#define GSM  207104

__device__ __forceinline__ float sig_(float v) { return 1.0f / (1.0f + expf(-v)); }

__global__ __launch_bounds__(256, 1) void gru(
    const float* __restrict__ Whr, const float* __restrict__ Whi, const float* __restrict__ Whn,
    float* __restrict__ out, int write_last)
{
    extern __shared__ __align__(16) char sm[];
    uint32_t sb = s2u(sm);
    float* Sacc = (float*)(sm + 196608);
    float* hown = (float*)(sm + 205056);
    int tid = threadIdx.x, lane = tid & 31, wid = tid >> 5;
    int wm = wid & 1, wn = wid >> 1;
    int c = blockIdx.x;

    // one-time resident W (32 n-rows: 24 real + 8 zero) x 1024 k, hi/lo
    #pragma unroll
    for (int i = 0; i < 16; i++) {
        int u = tid + i * 256;
        int n = u >> 7, un = u & 127;
        int k = un * 8;
        uint4 hi = make_uint4(0, 0, 0, 0), lo = hi;
        if (n < 24) {
            const float* W = (n < 8) ? Whr : (n < 16) ? Whi : Whn;
            const float* s = W + (size_t)(c * 8 + (n & 7)) * Hz + k;
            float4 a = *(const float4*)s, b = *(const float4*)(s + 4);
            cvt8(a, b, hi, lo);
        }
        uint32_t off = SWZ(((k >> 6) * 32 + n) * 128 + ((k >> 3) & 7) * 16);
        *(uint4*)(sm + off)         = hi;
        *(uint4*)(sm + 65536 + off) = lo;
    }
    if (tid < 64) {
        #pragma unroll
        for (int j = 0; j < 8; j++) hown[tid * 8 + j] = 0.0f;
    }
    __syncthreads();

    for (int t = 0; t < Tz; t++) {
        int par = t & 1, nxt = par ^ 1;
        const __nv_bfloat16* hhi = g_hhi[par];
        const __nv_bfloat16* hlo = g_hlo[par];

        float xr[8], xi[8], xn[8];
        if (tid < 64) {
            const float* xgrow = g_xg + (size_t)(tid * Tz + t) * G3z + c * 8;
            *(float4*)(xr)     = *(const float4*)(xgrow);
            *(float4*)(xr + 4) = *(const float4*)(xgrow + 4);
            *(float4*)(xi)     = *(const float4*)(xgrow + 1024);
            *(float4*)(xi + 4) = *(const float4*)(xgrow + 1028);
            *(float4*)(xn)     = *(const float4*)(xgrow + 2048);
            *(float4*)(xn + 4) = *(const float4*)(xgrow + 2052);
        }

        float acc[2][4];
        #pragma unroll
        for (int i = 0; i < 2; i++)
            #pragma unroll
            for (int j = 0; j < 4; j++) acc[i][j] = 0.0f;

        for (int kc = 0; kc < 8; kc++) {
            uint32_t ab = 131072 + (kc & 1) * 32768;
            #pragma unroll
            for (int i = 0; i < 4; i++) {               // 1024 units per buffer
                int u = tid + i * 256;
                int b = u >> 4, un = u & 15;
                size_t g = (size_t)b * Hz + kc * 128 + un * 8;
                uint32_t d = SWZ(((un >> 3) * 64 + b) * 128 + (un & 7) * 16);
                *(uint4*)(sm + ab + d)         = __ldcg((const uint4*)(hhi + g));
                *(uint4*)(sm + ab + 16384 + d) = __ldcg((const uint4*)(hlo + g));
            }
            __syncthreads();

            #pragma unroll
            for (int ks = 0; ks < 8; ks++) {
                uint32_t ah0[4], ah1[4], al0[4], al1[4], bh[2], bl[2];
                int kk = ks * 16 + (lane >> 4) * 8;
                int arow = wm * 32 + (lane & 7) + (lane & 8);
                uint32_t o0 = SWZ(((kk >> 6) * 64 + arow) * 128 + ((kk >> 3) & 7) * 16);
                uint32_t o1 = SWZ(((kk >> 6) * 64 + arow + 16) * 128 + ((kk >> 3) & 7) * 16);
                LDSM4(ah0, sb + ab + o0);          LDSM4(ah1, sb + ab + o1);
                LDSM4(al0, sb + ab + 16384 + o0);  LDSM4(al1, sb + ab + 16384 + o1);
                int bk = kc * 128 + ks * 16 + ((lane >> 3) & 1) * 8;
                int brow = wn * 8 + (lane & 7);
                uint32_t ob = SWZ(((bk >> 6) * 32 + brow) * 128 + ((bk >> 3) & 7) * 16);
                LDSM2(bh, sb + ob);
                LDSM2(bl, sb + 65536 + ob);
                MMA(acc[0], ah0, bh); MMA(acc[1], ah1, bh);
                MMA(acc[0], ah0, bl); MMA(acc[1], ah1, bl);
                MMA(acc[0], al0, bh); MMA(acc[1], al1, bh);
            }
        }

        // exchange partial gate pre-activations
        {
            int col = wn * 8 + 2 * (lane & 3);
            #pragma unroll
            for (int mt = 0; mt < 2; mt++) {
                int row = wm * 32 + mt * 16 + (lane >> 2);
                Sacc[row * 33 + col]           = acc[mt][0];
                Sacc[row * 33 + col + 1]       = acc[mt][1];
                Sacc[(row + 8) * 33 + col]     = acc[mt][2];
                Sacc[(row + 8) * 33 + col + 1] = acc[mt][3];
            }
        }
        __syncthreads();

        if (tid < 64) {
            int b = tid;
            float hn[8];
            #pragma unroll
            for (int j = 0; j < 8; j++) {
                float r  = sig_(xr[j] + Sacc[b * 33 + j]);
                float z  = sig_(xi[j] + Sacc[b * 33 + 8 + j]);
                float nn = tanhf(xn[j] + r * Sacc[b * 33 + 16 + j]);
                hn[j] = (1.0f - z) * nn + z * hown[b * 8 + j];
                hown[b * 8 + j] = hn[j];
            }
            float4 o0 = make_float4(hn[0], hn[1], hn[2], hn[3]);
            float4 o1 = make_float4(hn[4], hn[5], hn[6], hn[7]);
            float* orow = out + (size_t)(b * Tz + t) * Hz + c * 8;
            *(float4*)orow = o0;
            *(float4*)(orow + 4) = o1;
            if (write_last && t == Tz - 1) {
                float* lrow = out + (size_t)BTz * Hz + (size_t)b * Hz + c * 8;
                *(float4*)lrow = o0;
                *(float4*)(lrow + 4) = o1;
            }
            uint4 hi, lo;
            cvt8(o0, o1, hi, lo);
            __stcg((uint4*)(g_hhi[nxt] + (size_t)b * Hz + c * 8), hi);
            __stcg((uint4*)(g_hlo[nxt] + (size_t)b * Hz + c * 8), lo);
        }
        grid_sync_(NCTA);
    }
}

// ---------------- launch ----------------
extern "C" void kernel_launch(void* const* d_in, const int* in_sizes, int n_in,
                              void* d_out, int out_size) {
    const float* x   = (const float*)d_in[0];
    const float* Wir = (const float*)d_in[1];
    const float* Wii = (const float*)d_in[2];
    const float* Win = (const float*)d_in[3];
    const float* bir = (const float*)d_in[4];
    const float* bii = (const float*)d_in[5];
    const float* bin = (const float*)d_in[6];
    const float* Whr = (const float*)d_in[7];
    const float* Whi = (const float*)d_in[8];
    const float* Whn = (const float*)d_in[9];
    float* out = (float*)d_out;

    int write_last = (out_size >= BTz * Hz + Bz * Hz) ? 1 : 0;

    cudaFuncSetAttribute(xproj, cudaFuncAttributeMaxDynamicSharedMemorySize, 49152);
    cudaFuncSetAttribute(gru,   cudaFuncAttributeMaxDynamicSharedMemorySize, GSM);

    init_h<<<(Bz * Hz + 255) / 256, 256>>>();
    cvt_x<<<(int)(((size_t)BTz * INz / 8 + 255) / 256), 256>>>(x);
    cvt_w<<<(G3z * INz / 8 + 255) / 256, 256>>>(Wir, Wii, Win, bir, bii, bin);

    dim3 g1(BTz / 128, G3z / 64);
    xproj<<<g1, 256, 49152>>>();

    gru<<<NCTA, 256, GSM>>>(Whr, Whi, Whn, out, write_last);
}

// round 9
// speedup vs baseline: 2.1940x; 1.2082x over previous
#include <cuda_runtime.h>
#include <cuda_bf16.h>
#include <math.h>
#include <stdint.h>

#define Bz 64
#define Tz 512
#define INz 512
#define Hz 1024
#define G3z 3072
#define BTz 32768

__device__ __align__(16) float g_xg[(size_t)BTz * G3z];
__device__ __align__(16) __nv_bfloat16 g_xhi[(size_t)BTz * INz];
__device__ __align__(16) __nv_bfloat16 g_xlo[(size_t)BTz * INz];
__device__ __align__(16) __nv_bfloat16 g_whi[G3z * INz];
__device__ __align__(16) __nv_bfloat16 g_wlo[G3z * INz];
__device__ __align__(16) float g_bias[G3z];
__device__ __align__(16) __nv_bfloat16 g_hhi[2][Bz * Hz];
__device__ __align__(16) __nv_bfloat16 g_hlo[2][Bz * Hz];
__device__ unsigned g_bc, g_bg;

// ---------------- helpers ----------------
__device__ __forceinline__ uint32_t s2u(const void* p) {
    uint32_t a;
    asm("{ .reg .u64 t; cvta.to.shared.u64 t, %1; cvt.u32.u64 %0, t; }" : "=r"(a) : "l"(p));
    return a;
}
#define SWZ(o) ((uint32_t)(o) ^ (((uint32_t)(o) >> 3) & 0x70u))

#define LDSM4(r, a) asm volatile("ldmatrix.sync.aligned.m8n8.x4.shared.b16 {%0,%1,%2,%3}, [%4];" \
    : "=r"((r)[0]), "=r"((r)[1]), "=r"((r)[2]), "=r"((r)[3]) : "r"(a))
#define LDSM2(r, a) asm volatile("ldmatrix.sync.aligned.m8n8.x2.shared.b16 {%0,%1}, [%2];" \
    : "=r"((r)[0]), "=r"((r)[1]) : "r"(a))
#define MMA(d, a, b) asm volatile( \
    "mma.sync.aligned.m16n8k16.row.col.f32.bf16.bf16.f32 " \
    "{%0,%1,%2,%3}, {%4,%5,%6,%7}, {%8,%9}, {%0,%1,%2,%3};" \
    : "+f"((d)[0]), "+f"((d)[1]), "+f"((d)[2]), "+f"((d)[3]) \
    : "r"((a)[0]), "r"((a)[1]), "r"((a)[2]), "r"((a)[3]), "r"((b)[0]), "r"((b)[1]))

#define CP16(s, g) asm volatile("cp.async.cg.shared.global [%0], [%1], 16;" :: "r"(s), "l"(g) : "memory")
#define CPCOMMIT() asm volatile("cp.async.commit_group;" ::: "memory")
#define CPWAIT0()  asm volatile("cp.async.wait_group 0;" ::: "memory")

__device__ __forceinline__ void cvt8(float4 v0, float4 v1, uint4& hi, uint4& lo) {
    float f[8] = {v0.x, v0.y, v0.z, v0.w, v1.x, v1.y, v1.z, v1.w};
    uint32_t h[4], l[4];
    #pragma unroll
    for (int i = 0; i < 4; i++) {
        __nv_bfloat16 a = __float2bfloat16(f[2*i]), b = __float2bfloat16(f[2*i+1]);
        __nv_bfloat16 al = __float2bfloat16(f[2*i] - __bfloat162float(a));
        __nv_bfloat16 bl = __float2bfloat16(f[2*i+1] - __bfloat162float(b));
        __nv_bfloat162 hp = __halves2bfloat162(a, b), lp = __halves2bfloat162(al, bl);
        h[i] = *reinterpret_cast<uint32_t*>(&hp);
        l[i] = *reinterpret_cast<uint32_t*>(&lp);
    }
    hi = make_uint4(h[0], h[1], h[2], h[3]);
    lo = make_uint4(l[0], l[1], l[2], l[3]);
}

__device__ __forceinline__ void grid_sync_(int n) {
    __threadfence();
    __syncthreads();
    if (threadIdx.x == 0) {
        unsigned gen = atomicAdd(&g_bg, 0u);
        if (atomicAdd(&g_bc, 1u) == (unsigned)(n - 1)) {
            g_bc = 0u;
            __threadfence();
            atomicAdd(&g_bg, 1u);
        } else {
            while (atomicAdd(&g_bg, 0u) == gen) { __nanosleep(64); }
        }
    }
    __syncthreads();
}

// ---------------- one-time converts ----------------
__global__ void cvt_x(const float* __restrict__ x) {
    size_t u = (size_t)blockIdx.x * 256 + threadIdx.x;   // 16B unit (8 elems)
    if (u < (size_t)BTz * INz / 8) {
        float4 a = *(const float4*)(x + u * 8);
        float4 b = *(const float4*)(x + u * 8 + 4);
        uint4 hi, lo; cvt8(a, b, hi, lo);
        *(uint4*)(g_xhi + u * 8) = hi;
        *(uint4*)(g_xlo + u * 8) = lo;
    }
}

__global__ void cvt_w(const float* __restrict__ Wir, const float* __restrict__ Wii, const float* __restrict__ Win,
                      const float* __restrict__ bir, const float* __restrict__ bii, const float* __restrict__ bin) {
    int u = blockIdx.x * 256 + threadIdx.x;
    if (u < G3z * INz / 8) {
        int row = u >> 6, un = u & 63;
        int gate = row >> 10, r = row & 1023;
        const float* W = (gate == 0) ? Wir : (gate == 1) ? Wii : Win;
        const float* s = W + (size_t)r * INz + un * 8;
        float4 a = *(const float4*)s, b = *(const float4*)(s + 4);
        uint4 hi, lo; cvt8(a, b, hi, lo);
        *(uint4*)(g_whi + (size_t)u * 8) = hi;
        *(uint4*)(g_wlo + (size_t)u * 8) = lo;
    }
    if (u < G3z) {
        int gate = u >> 10;
        const float* bb = (gate == 0) ? bir : (gate == 1) ? bii : bin;
        g_bias[u] = bb[u & 1023];
    }
}

__global__ void init_h() {
    int i = blockIdx.x * blockDim.x + threadIdx.x;
    if (i < Bz * Hz) {
        g_hhi[0][i] = __float2bfloat16(0.0f);
        g_hlo[0][i] = __float2bfloat16(0.0f);
    }
}

// ---------------- phase 1: xg = x @ Wi^T + b (mma.sync bf16 hi/lo) ----------------
// smem: AH 0 (16K) | AL 16384 | BH 32768 (8K) | BL 40960 | total 49152
__global__ __launch_bounds__(256, 2) void xproj(void) {
    extern __shared__ __align__(16) char sm[];
    uint32_t sb = s2u(sm);
    int tid = threadIdx.x, lane = tid & 31, wid = tid >> 5;
    int m0 = blockIdx.x * 128;
    int n0 = blockIdx.y * 64;
    int wm = wid >> 1, wn = wid & 1;

    float acc[2][4][4];
    #pragma unroll
    for (int i = 0; i < 2; i++)
        #pragma unroll
        for (int j = 0; j < 4; j++)
            #pragma unroll
            for (int k = 0; k < 4; k++) acc[i][j][k] = 0.0f;

    for (int kc = 0; kc < 8; kc++) {
        int k0 = kc * 64;
        #pragma unroll
        for (int i = 0; i < 4; i++) {                     // A: 1024 units
            int u = tid + i * 256;
            int row = u >> 3, un = u & 7;
            size_t g = (size_t)(m0 + row) * INz + k0 + un * 8;
            uint32_t d = SWZ(row * 128 + un * 16);
            *(uint4*)(sm + d)          = *(const uint4*)(g_xhi + g);
            *(uint4*)(sm + 16384 + d)  = *(const uint4*)(g_xlo + g);
        }
        #pragma unroll
        for (int i = 0; i < 2; i++) {                     // B: 512 units
            int u = tid + i * 256;
            int row = u >> 3, un = u & 7;
            size_t g = (size_t)(n0 + row) * INz + k0 + un * 8;
            uint32_t d = SWZ(row * 128 + un * 16);
            *(uint4*)(sm + 32768 + d)  = *(const uint4*)(g_whi + g);
            *(uint4*)(sm + 40960 + d)  = *(const uint4*)(g_wlo + g);
        }
        __syncthreads();

        #pragma unroll
        for (int ks = 0; ks < 4; ks++) {
            uint32_t ah0[4], ah1[4], al0[4], al1[4], bh[8], bl[8];
            int arow = wm * 32 + (lane & 7) + (lane & 8);
            int aku  = ks * 2 + (lane >> 4);
            uint32_t o0 = SWZ(arow * 128 + aku * 16);
            uint32_t o1 = SWZ((arow + 16) * 128 + aku * 16);
            LDSM4(ah0, sb + o0);          LDSM4(ah1, sb + o1);
            LDSM4(al0, sb + 16384 + o0);  LDSM4(al1, sb + 16384 + o1);
            int brow = wn * 32 + (lane & 7) + ((lane >> 4) & 1) * 8;
            int bku  = ks * 2 + ((lane >> 3) & 1);
            uint32_t p0 = SWZ(brow * 128 + bku * 16);
            uint32_t p1 = SWZ((brow + 16) * 128 + bku * 16);
            LDSM4(bh,     sb + 32768 + p0);  LDSM4(bh + 4, sb + 32768 + p1);
            LDSM4(bl,     sb + 40960 + p0);  LDSM4(bl + 4, sb + 40960 + p1);
            #pragma unroll
            for (int nt = 0; nt < 4; nt++) {
                MMA(acc[0][nt], ah0, bh + nt * 2);
                MMA(acc[1][nt], ah1, bh + nt * 2);
                MMA(acc[0][nt], ah0, bl + nt * 2);
                MMA(acc[1][nt], ah1, bl + nt * 2);
                MMA(acc[0][nt], al0, bh + nt * 2);
                MMA(acc[1][nt], al1, bh + nt * 2);
            }
        }
        __syncthreads();
    }

    #pragma unroll
    for (int mt = 0; mt < 2; mt++)
        #pragma unroll
        for (int nt = 0; nt < 4; nt++) {
            int m = m0 + wm * 32 + mt * 16 + (lane >> 2);
            int n = n0 + wn * 32 + nt * 8 + 2 * (lane & 3);
            float b0 = __ldg(g_bias + n), b1 = __ldg(g_bias + n + 1);
            *(float2*)(g_xg + (size_t)m * G3z + n)       = make_float2(acc[mt][nt][0] + b0, acc[mt][nt][1] + b1);
            *(float2*)(g_xg + (size_t)(m + 8) * G3z + n) = make_float2(acc[mt][nt][2] + b0, acc[mt][nt][3] + b1);
        }
}

// ---------------- phase 2: persistent recurrence (mma.sync bf16 hi/lo, cp.async pipelined) ----------------
// smem: WH 0 (64K) | WL 65536 | A0H 131072 | A0L 147456 | A1H 163840 | A1L 180224
//       Sacc 196608 (64*33*4=8448) | hown 205056 (2048) | total 207104
#define NCTA 128
#define GSM  207104

__device__ __forceinline__ float sig_(float v) { return 1.0f / (1.0f + expf(-v)); }

// issue cp.async.cg fills for one 64x128 h K-tile (hi+lo), no commit
__device__ __forceinline__ void fill_h(uint32_t sb, uint32_t ab,
                                       const __nv_bfloat16* hhi, const __nv_bfloat16* hlo,
                                       int kc, int tid) {
    #pragma unroll
    for (int i = 0; i < 4; i++) {
        int u = tid + i * 256;
        int b = u >> 4, un = u & 15;
        size_t g = (size_t)b * Hz + kc * 128 + un * 8;
        uint32_t d = SWZ(((un >> 3) * 64 + b) * 128 + (un & 7) * 16);
        CP16(sb + ab + d,         hhi + g);
        CP16(sb + ab + 16384 + d, hlo + g);
    }
}

__global__ __launch_bounds__(256, 1) void gru(
    const float* __restrict__ Whr, const float* __restrict__ Whi, const float* __restrict__ Whn,
    float* __restrict__ out, int write_last)
{
    extern __shared__ __align__(16) char sm[];
    uint32_t sb = s2u(sm);
    float* Sacc = (float*)(sm + 196608);
    float* hown = (float*)(sm + 205056);
    int tid = threadIdx.x, lane = tid & 31, wid = tid >> 5;
    int wm = wid & 1, wn = wid >> 1;
    int c = blockIdx.x;

    // one-time resident W (32 n-rows: 24 real + 8 zero) x 1024 k, hi/lo
    #pragma unroll
    for (int i = 0; i < 16; i++) {
        int u = tid + i * 256;
        int n = u >> 7, un = u & 127;
        int k = un * 8;
        uint4 hi = make_uint4(0, 0, 0, 0), lo = hi;
        if (n < 24) {
            const float* W = (n < 8) ? Whr : (n < 16) ? Whi : Whn;
            const float* s = W + (size_t)(c * 8 + (n & 7)) * Hz + k;
            float4 a = *(const float4*)s, b = *(const float4*)(s + 4);
            cvt8(a, b, hi, lo);
        }
        uint32_t off = SWZ(((k >> 6) * 32 + n) * 128 + ((k >> 3) & 7) * 16);
        *(uint4*)(sm + off)         = hi;
        *(uint4*)(sm + 65536 + off) = lo;
    }
    if (tid < 64) {
        #pragma unroll
        for (int j = 0; j < 8; j++) hown[tid * 8 + j] = 0.0f;
    }
    __syncthreads();

    for (int t = 0; t < Tz; t++) {
        int par = t & 1, nxt = par ^ 1;
        const __nv_bfloat16* hhi = g_hhi[par];
        const __nv_bfloat16* hlo = g_hlo[par];

        // kick off first h K-tile for this step
        fill_h(sb, 131072, hhi, hlo, 0, tid);
        CPCOMMIT();

        float xr[8], xi[8], xn[8];
        if (tid < 64) {
            const float* xgrow = g_xg + (size_t)(tid * Tz + t) * G3z + c * 8;
            *(float4*)(xr)     = *(const float4*)(xgrow);
            *(float4*)(xr + 4) = *(const float4*)(xgrow + 4);
            *(float4*)(xi)     = *(const float4*)(xgrow + 1024);
            *(float4*)(xi + 4) = *(const float4*)(xgrow + 1028);
            *(float4*)(xn)     = *(const float4*)(xgrow + 2048);
            *(float4*)(xn + 4) = *(const float4*)(xgrow + 2052);
        }

        float acc[2][4];
        #pragma unroll
        for (int i = 0; i < 2; i++)
            #pragma unroll
            for (int j = 0; j < 4; j++) acc[i][j] = 0.0f;

        for (int kc = 0; kc < 8; kc++) {
            CPWAIT0();                 // current buffer's group done
            __syncthreads();           // visible to all warps; prev buffer fully read
            if (kc < 7) {              // prefetch next tile into other buffer (overlaps MMA below)
                fill_h(sb, 131072 + ((kc + 1) & 1) * 32768, hhi, hlo, kc + 1, tid);
                CPCOMMIT();
            }
            uint32_t ab = 131072 + (kc & 1) * 32768;

            #pragma unroll
            for (int ks = 0; ks < 8; ks++) {
                uint32_t ah0[4], ah1[4], al0[4], al1[4], bh[2], bl[2];
                int kk = ks * 16 + (lane >> 4) * 8;
                int arow = wm * 32 + (lane & 7) + (lane & 8);
                uint32_t o0 = SWZ(((kk >> 6) * 64 + arow) * 128 + ((kk >> 3) & 7) * 16);
                uint32_t o1 = SWZ(((kk >> 6) * 64 + arow + 16) * 128 + ((kk >> 3) & 7) * 16);
                LDSM4(ah0, sb + ab + o0);          LDSM4(ah1, sb + ab + o1);
                LDSM4(al0, sb + ab + 16384 + o0);  LDSM4(al1, sb + ab + 16384 + o1);
                int bk = kc * 128 + ks * 16 + ((lane >> 3) & 1) * 8;
                int brow = wn * 8 + (lane & 7);
                uint32_t ob = SWZ(((bk >> 6) * 32 + brow) * 128 + ((bk >> 3) & 7) * 16);
                LDSM2(bh, sb + ob);
                LDSM2(bl, sb + 65536 + ob);
                MMA(acc[0], ah0, bh); MMA(acc[1], ah1, bh);
                MMA(acc[0], ah0, bl); MMA(acc[1], ah1, bl);
                MMA(acc[0], al0, bh); MMA(acc[1], al1, bh);
            }
        }

        // exchange partial gate pre-activations
        {
            int col = wn * 8 + 2 * (lane & 3);
            #pragma unroll
            for (int mt = 0; mt < 2; mt++) {
                int row = wm * 32 + mt * 16 + (lane >> 2);
                Sacc[row * 33 + col]           = acc[mt][0];
                Sacc[row * 33 + col + 1]       = acc[mt][1];
                Sacc[(row + 8) * 33 + col]     = acc[mt][2];
                Sacc[(row + 8) * 33 + col + 1] = acc[mt][3];
            }
        }
        __syncthreads();

        if (tid < 64) {
            int b = tid;
            float hn[8];
            #pragma unroll
            for (int j = 0; j < 8; j++) {
                float r  = sig_(xr[j] + Sacc[b * 33 + j]);
                float z  = sig_(xi[j] + Sacc[b * 33 + 8 + j]);
                float nn = tanhf(xn[j] + r * Sacc[b * 33 + 16 + j]);
                hn[j] = (1.0f - z) * nn + z * hown[b * 8 + j];
                hown[b * 8 + j] = hn[j];
            }
            float4 o0 = make_float4(hn[0], hn[1], hn[2], hn[3]);
            float4 o1 = make_float4(hn[4], hn[5], hn[6], hn[7]);
            float* orow = out + (size_t)(b * Tz + t) * Hz + c * 8;
            *(float4*)orow = o0;
            *(float4*)(orow + 4) = o1;
            if (write_last && t == Tz - 1) {
                float* lrow = out + (size_t)BTz * Hz + (size_t)b * Hz + c * 8;
                *(float4*)lrow = o0;
                *(float4*)(lrow + 4) = o1;
            }
            uint4 hi, lo;
            cvt8(o0, o1, hi, lo);
            __stcg((uint4*)(g_hhi[nxt] + (size_t)b * Hz + c * 8), hi);
            __stcg((uint4*)(g_hlo[nxt] + (size_t)b * Hz + c * 8), lo);
        }
        grid_sync_(NCTA);
    }
}

// ---------------- launch ----------------
extern "C" void kernel_launch(void* const* d_in, const int* in_sizes, int n_in,
                              void* d_out, int out_size) {
    const float* x   = (const float*)d_in[0];
    const float* Wir = (const float*)d_in[1];
    const float* Wii = (const float*)d_in[2];
    const float* Win = (const float*)d_in[3];
    const float* bir = (const float*)d_in[4];
    const float* bii = (const float*)d_in[5];
    const float* bin = (const float*)d_in[6];
    const float* Whr = (const float*)d_in[7];
    const float* Whi = (const float*)d_in[8];
    const float* Whn = (const float*)d_in[9];
    float* out = (float*)d_out;

    int write_last = (out_size >= BTz * Hz + Bz * Hz) ? 1 : 0;

    cudaFuncSetAttribute(xproj, cudaFuncAttributeMaxDynamicSharedMemorySize, 49152);
    cudaFuncSetAttribute(gru,   cudaFuncAttributeMaxDynamicSharedMemorySize, GSM);

    init_h<<<(Bz * Hz + 255) / 256, 256>>>();
    cvt_x<<<(int)(((size_t)BTz * INz / 8 + 255) / 256), 256>>>(x);
    cvt_w<<<(G3z * INz / 8 + 255) / 256, 256>>>(Wir, Wii, Win, bir, bii, bin);

    dim3 g1(BTz / 128, G3z / 64);
    xproj<<<g1, 256, 49152>>>();

    gru<<<NCTA, 256, GSM>>>(Whr, Whi, Whn, out, write_last);
}

// round 10
// speedup vs baseline: 2.7472x; 1.2521x over previous
#include <cuda_runtime.h>
#include <cuda_bf16.h>
#include <math.h>
#include <stdint.h>

#define Bz 64
#define Tz 512
#define INz 512
#define Hz 1024
#define G3z 3072
#define BTz 32768

__device__ __align__(16) float g_xg[(size_t)BTz * G3z];
__device__ __align__(16) __nv_bfloat16 g_xhi[(size_t)BTz * INz];
__device__ __align__(16) __nv_bfloat16 g_xlo[(size_t)BTz * INz];
__device__ __align__(16) __nv_bfloat16 g_whi[G3z * INz];
__device__ __align__(16) __nv_bfloat16 g_wlo[G3z * INz];
__device__ __align__(16) float g_bias[G3z];
__device__ __align__(16) __nv_bfloat16 g_hhi[2][Bz * Hz];
__device__ __align__(16) __nv_bfloat16 g_hlo[2][Bz * Hz];
__device__ unsigned g_bc1[8];
__device__ unsigned g_bc2;
__device__ unsigned g_bg;

// ---------------- helpers ----------------
__device__ __forceinline__ uint32_t s2u(const void* p) {
    uint32_t a;
    asm("{ .reg .u64 t; cvta.to.shared.u64 t, %1; cvt.u32.u64 %0, t; }" : "=r"(a) : "l"(p));
    return a;
}
#define SWZ(o) ((uint32_t)(o) ^ (((uint32_t)(o) >> 3) & 0x70u))

#define LDSM4(r, a) asm volatile("ldmatrix.sync.aligned.m8n8.x4.shared.b16 {%0,%1,%2,%3}, [%4];" \
    : "=r"((r)[0]), "=r"((r)[1]), "=r"((r)[2]), "=r"((r)[3]) : "r"(a))
#define LDSM2(r, a) asm volatile("ldmatrix.sync.aligned.m8n8.x2.shared.b16 {%0,%1}, [%2];" \
    : "=r"((r)[0]), "=r"((r)[1]) : "r"(a))
#define MMA(d, a, b) asm volatile( \
    "mma.sync.aligned.m16n8k16.row.col.f32.bf16.bf16.f32 " \
    "{%0,%1,%2,%3}, {%4,%5,%6,%7}, {%8,%9}, {%0,%1,%2,%3};" \
    : "+f"((d)[0]), "+f"((d)[1]), "+f"((d)[2]), "+f"((d)[3]) \
    : "r"((a)[0]), "r"((a)[1]), "r"((a)[2]), "r"((a)[3]), "r"((b)[0]), "r"((b)[1]))

#define CP16(s, g) asm volatile("cp.async.cg.shared.global [%0], [%1], 16;" :: "r"(s), "l"(g) : "memory")
#define CPCOMMIT() asm volatile("cp.async.commit_group;" ::: "memory")
#define CPWAIT0()  asm volatile("cp.async.wait_group 0;" ::: "memory")

__device__ __forceinline__ void cvt8(float4 v0, float4 v1, uint4& hi, uint4& lo) {
    float f[8] = {v0.x, v0.y, v0.z, v0.w, v1.x, v1.y, v1.z, v1.w};
    uint32_t h[4], l[4];
    #pragma unroll
    for (int i = 0; i < 4; i++) {
        __nv_bfloat16 a = __float2bfloat16(f[2*i]), b = __float2bfloat16(f[2*i+1]);
        __nv_bfloat16 al = __float2bfloat16(f[2*i] - __bfloat162float(a));
        __nv_bfloat16 bl = __float2bfloat16(f[2*i+1] - __bfloat162float(b));
        __nv_bfloat162 hp = __halves2bfloat162(a, b), lp = __halves2bfloat162(al, bl);
        h[i] = *reinterpret_cast<uint32_t*>(&hp);
        l[i] = *reinterpret_cast<uint32_t*>(&lp);
    }
    hi = make_uint4(h[0], h[1], h[2], h[3]);
    lo = make_uint4(l[0], l[1], l[2], l[3]);
}

// tree grid barrier: 8 groups of 16 CTAs, monotonic counters (zeroed in init_h each launch)
__device__ __forceinline__ void grid_sync_t(int t, int c) {
    __syncthreads();
    if (threadIdx.x == 0) {
        asm volatile("fence.acq_rel.gpu;" ::: "memory");
        unsigned tgt = (unsigned)(t + 1);
        int g = c >> 4;
        bool done = false;
        if (atomicAdd(&g_bc1[g], 1u) == (unsigned)(t * 16 + 15)) {
            if (atomicAdd(&g_bc2, 1u) == (unsigned)(t * 8 + 7)) {
                asm volatile("fence.acq_rel.gpu;" ::: "memory");
                asm volatile("st.release.gpu.global.u32 [%0], %1;" :: "l"(&g_bg), "r"(tgt) : "memory");
                done = true;
            }
        }
        if (!done) {
            unsigned v;
            do {
                __nanosleep(32);
                asm volatile("ld.acquire.gpu.global.u32 %0, [%1];" : "=r"(v) : "l"(&g_bg));
            } while (v < tgt);
        }
    }
    __syncthreads();
}

// ---------------- one-time converts / init ----------------
__global__ void init_h() {
    int i = blockIdx.x * blockDim.x + threadIdx.x;
    if (i < Bz * Hz) {
        g_hhi[0][i] = __float2bfloat16(0.0f);
        g_hlo[0][i] = __float2bfloat16(0.0f);
    }
    if (i < 8) g_bc1[i] = 0u;
    if (i == 8) g_bc2 = 0u;
    if (i == 9) g_bg = 0u;
}

__global__ void cvt_x(const float* __restrict__ x) {
    size_t u = (size_t)blockIdx.x * 256 + threadIdx.x;
    if (u < (size_t)BTz * INz / 8) {
        float4 a = *(const float4*)(x + u * 8);
        float4 b = *(const float4*)(x + u * 8 + 4);
        uint4 hi, lo; cvt8(a, b, hi, lo);
        *(uint4*)(g_xhi + u * 8) = hi;
        *(uint4*)(g_xlo + u * 8) = lo;
    }
}

__global__ void cvt_w(const float* __restrict__ Wir, const float* __restrict__ Wii, const float* __restrict__ Win,
                      const float* __restrict__ bir, const float* __restrict__ bii, const float* __restrict__ bin) {
    int u = blockIdx.x * 256 + threadIdx.x;
    if (u < G3z * INz / 8) {
        int row = u >> 6, un = u & 63;
        int gate = row >> 10, r = row & 1023;
        const float* W = (gate == 0) ? Wir : (gate == 1) ? Wii : Win;
        const float* s = W + (size_t)r * INz + un * 8;
        float4 a = *(const float4*)s, b = *(const float4*)(s + 4);
        uint4 hi, lo; cvt8(a, b, hi, lo);
        *(uint4*)(g_whi + (size_t)u * 8) = hi;
        *(uint4*)(g_wlo + (size_t)u * 8) = lo;
    }
    if (u < G3z) {
        int gate = u >> 10;
        const float* bb = (gate == 0) ? bir : (gate == 1) ? bii : bin;
        g_bias[u] = bb[u & 1023];
    }
}

// ---------------- phase 1: xg = x @ Wi^T + b (cp.async double-buffered) ----------------
// per buffer: AH 0 | AL 16384 | BH 32768 | BL 40960  (48K); two buffers = 96K
#define XBUF 49152
#define XSM  98304

__device__ __forceinline__ void xfill(uint32_t sb, uint32_t ab, int m0, int n0, int kc, int tid) {
    int k0 = kc * 64;
    #pragma unroll
    for (int i = 0; i < 4; i++) {                 // A: 1024 units
        int u = tid + i * 256;
        int row = u >> 3, un = u & 7;
        size_t g = (size_t)(m0 + row) * INz + k0 + un * 8;
        uint32_t d = SWZ(row * 128 + un * 16);
        CP16(sb + ab + d,         g_xhi + g);
        CP16(sb + ab + 16384 + d, g_xlo + g);
    }
    #pragma unroll
    for (int i = 0; i < 2; i++) {                 // B: 512 units
        int u = tid + i * 256;
        int row = u >> 3, un = u & 7;
        size_t g = (size_t)(n0 + row) * INz + k0 + un * 8;
        uint32_t d = SWZ(row * 128 + un * 16);
        CP16(sb + ab + 32768 + d, g_whi + g);
        CP16(sb + ab + 40960 + d, g_wlo + g);
    }
}

__global__ __launch_bounds__(256, 2) void xproj(void) {
    extern __shared__ __align__(16) char sm[];
    uint32_t sb = s2u(sm);
    int tid = threadIdx.x, lane = tid & 31, wid = tid >> 5;
    int m0 = blockIdx.x * 128;
    int n0 = blockIdx.y * 64;
    int wm = wid >> 1, wn = wid & 1;

    float acc[2][4][4];
    #pragma unroll
    for (int i = 0; i < 2; i++)
        #pragma unroll
        for (int j = 0; j < 4; j++)
            #pragma unroll
            for (int k = 0; k < 4; k++) acc[i][j][k] = 0.0f;

    xfill(sb, 0, m0, n0, 0, tid);
    CPCOMMIT();

    for (int kc = 0; kc < 8; kc++) {
        CPWAIT0();
        __syncthreads();
        if (kc < 7) {
            xfill(sb, ((kc + 1) & 1) * XBUF, m0, n0, kc + 1, tid);
            CPCOMMIT();
        }
        uint32_t ab = (kc & 1) * XBUF;

        #pragma unroll
        for (int ks = 0; ks < 4; ks++) {
            uint32_t ah0[4], ah1[4], al0[4], al1[4], bh[8], bl[8];
            int arow = wm * 32 + (lane & 7) + (lane & 8);
            int aku  = ks * 2 + (lane >> 4);
            uint32_t o0 = SWZ(arow * 128 + aku * 16);
            uint32_t o1 = SWZ((arow + 16) * 128 + aku * 16);
            LDSM4(ah0, sb + ab + o0);          LDSM4(ah1, sb + ab + o1);
            LDSM4(al0, sb + ab + 16384 + o0);  LDSM4(al1, sb + ab + 16384 + o1);
            int brow = wn * 32 + (lane & 7) + ((lane >> 4) & 1) * 8;
            int bku  = ks * 2 + ((lane >> 3) & 1);
            uint32_t p0 = SWZ(brow * 128 + bku * 16);
            uint32_t p1 = SWZ((brow + 16) * 128 + bku * 16);
            LDSM4(bh,     sb + ab + 32768 + p0);  LDSM4(bh + 4, sb + ab + 32768 + p1);
            LDSM4(bl,     sb + ab + 40960 + p0);  LDSM4(bl + 4, sb + ab + 40960 + p1);
            #pragma unroll
            for (int nt = 0; nt < 4; nt++) {
                MMA(acc[0][nt], ah0, bh + nt * 2);
                MMA(acc[1][nt], ah1, bh + nt * 2);
                MMA(acc[0][nt], ah0, bl + nt * 2);
                MMA(acc[1][nt], ah1, bl + nt * 2);
                MMA(acc[0][nt], al0, bh + nt * 2);
                MMA(acc[1][nt], al1, bh + nt * 2);
            }
        }
    }

    #pragma unroll
    for (int mt = 0; mt < 2; mt++)
        #pragma unroll
        for (int nt = 0; nt < 4; nt++) {
            int m = m0 + wm * 32 + mt * 16 + (lane >> 2);
            int n = n0 + wn * 32 + nt * 8 + 2 * (lane & 3);
            float b0 = __ldg(g_bias + n), b1 = __ldg(g_bias + n + 1);
            *(float2*)(g_xg + (size_t)m * G3z + n)       = make_float2(acc[mt][nt][0] + b0, acc[mt][nt][1] + b1);
            *(float2*)(g_xg + (size_t)(m + 8) * G3z + n) = make_float2(acc[mt][nt][2] + b0, acc[mt][nt][3] + b1);
        }
}

// ---------------- phase 2: persistent recurrence ----------------
// smem: WH 0 (64K) | WL 65536 | A0H 131072 | A0L 147456 | A1H 163840 | A1L 180224
//       Sacc 196608 (64*33*4=8448) | hown 205056 (2048) | total 207104
#define NCTA 128
#define GSM  207104

__device__ __forceinline__ float sigf(float v)  { return __fdividef(1.0f, 1.0f + __expf(-v)); }
__device__ __forceinline__ float tanhf_(float v) { return 1.0f - __fdividef(2.0f, __expf(2.0f * v) + 1.0f); }

// fills issued by 64 threads (tl = 0..63)
__device__ __forceinline__ void fill_h64(uint32_t sb, uint32_t ab,
                                         const __nv_bfloat16* hhi, const __nv_bfloat16* hlo,
                                         int kc, int tl) {
    #pragma unroll
    for (int i = 0; i < 16; i++) {
        int u = tl + i * 64;
        int b = u >> 4, un = u & 15;
        size_t g = (size_t)b * Hz + kc * 128 + un * 8;
        uint32_t d = SWZ(((un >> 3) * 64 + b) * 128 + (un & 7) * 16);
        CP16(sb + ab + d,         hhi + g);
        CP16(sb + ab + 16384 + d, hlo + g);
    }
}

__global__ __launch_bounds__(256, 1) void gru(
    const float* __restrict__ Whr, const float* __restrict__ Whi, const float* __restrict__ Whn,
    float* __restrict__ out, int write_last)
{
    extern __shared__ __align__(16) char sm[];
    uint32_t sb = s2u(sm);
    float* Sacc = (float*)(sm + 196608);
    float* hown = (float*)(sm + 205056);
    int tid = threadIdx.x, lane = tid & 31, wid = tid >> 5;
    int wm = wid & 1, wn = wid >> 1;     // wn==3 (wid 6,7) = filler warps
    int c = blockIdx.x;

    // one-time resident W (32 n-rows: 24 real + 8 zero) x 1024 k, hi/lo
    #pragma unroll
    for (int i = 0; i < 16; i++) {
        int u = tid + i * 256;
        int n = u >> 7, un = u & 127;
        int k = un * 8;
        uint4 hi = make_uint4(0, 0, 0, 0), lo = hi;
        if (n < 24) {
            const float* W = (n < 8) ? Whr : (n < 16) ? Whi : Whn;
            const float* s = W + (size_t)(c * 8 + (n & 7)) * Hz + k;
            float4 a = *(const float4*)s, b = *(const float4*)(s + 4);
            cvt8(a, b, hi, lo);
        }
        uint32_t off = SWZ(((k >> 6) * 32 + n) * 128 + ((k >> 3) & 7) * 16);
        *(uint4*)(sm + off)         = hi;
        *(uint4*)(sm + 65536 + off) = lo;
    }
    if (tid < 64) {
        #pragma unroll
        for (int j = 0; j < 8; j++) hown[tid * 8 + j] = 0.0f;
    }
    __syncthreads();

    for (int t = 0; t < Tz; t++) {
        int par = t & 1, nxt = par ^ 1;
        const __nv_bfloat16* hhi = g_hhi[par];
        const __nv_bfloat16* hlo = g_hlo[par];

        if (tid >= 192) fill_h64(sb, 131072, hhi, hlo, 0, tid - 192);
        CPCOMMIT();

        float xr[8], xi[8], xn[8];
        if (tid < 64) {
            const float* xgrow = g_xg + (size_t)(tid * Tz + t) * G3z + c * 8;
            *(float4*)(xr)     = *(const float4*)(xgrow);
            *(float4*)(xr + 4) = *(const float4*)(xgrow + 4);
            *(float4*)(xi)     = *(const float4*)(xgrow + 1024);
            *(float4*)(xi + 4) = *(const float4*)(xgrow + 1028);
            *(float4*)(xn)     = *(const float4*)(xgrow + 2048);
            *(float4*)(xn + 4) = *(const float4*)(xgrow + 2052);
        }

        float acc[2][4];
        #pragma unroll
        for (int i = 0; i < 2; i++)
            #pragma unroll
            for (int j = 0; j < 4; j++) acc[i][j] = 0.0f;

        for (int kc = 0; kc < 8; kc++) {
            CPWAIT0();
            __syncthreads();
            if (kc < 7 && tid >= 192)
                fill_h64(sb, 131072 + ((kc + 1) & 1) * 32768, hhi, hlo, kc + 1, tid - 192);
            CPCOMMIT();
            uint32_t ab = 131072 + (kc & 1) * 32768;

            if (wn < 3) {
                #pragma unroll
                for (int ks = 0; ks < 8; ks++) {
                    uint32_t ah0[4], ah1[4], al0[4], al1[4], bh[2], bl[2];
                    int kk = ks * 16 + (lane >> 4) * 8;
                    int arow = wm * 32 + (lane & 7) + (lane & 8);
                    uint32_t o0 = SWZ(((kk >> 6) * 64 + arow) * 128 + ((kk >> 3) & 7) * 16);
                    uint32_t o1 = SWZ(((kk >> 6) * 64 + arow + 16) * 128 + ((kk >> 3) & 7) * 16);
                    LDSM4(ah0, sb + ab + o0);          LDSM4(ah1, sb + ab + o1);
                    LDSM4(al0, sb + ab + 16384 + o0);  LDSM4(al1, sb + ab + 16384 + o1);
                    int bk = kc * 128 + ks * 16 + ((lane >> 3) & 1) * 8;
                    int brow = wn * 8 + (lane & 7);
                    uint32_t ob = SWZ(((bk >> 6) * 32 + brow) * 128 + ((bk >> 3) & 7) * 16);
                    LDSM2(bh, sb + ob);
                    LDSM2(bl, sb + 65536 + ob);
                    MMA(acc[0], ah0, bh); MMA(acc[1], ah1, bh);
                    MMA(acc[0], ah0, bl); MMA(acc[1], ah1, bl);
                    MMA(acc[0], al0, bh); MMA(acc[1], al1, bh);
                }
            }
        }

        // exchange partial gate pre-activations (real 24 cols only)
        if (wn < 3) {
            int col = wn * 8 + 2 * (lane & 3);
            #pragma unroll
            for (int mt = 0; mt < 2; mt++) {
                int row = wm * 32 + mt * 16 + (lane >> 2);
                Sacc[row * 33 + col]           = acc[mt][0];
                Sacc[row * 33 + col + 1]       = acc[mt][1];
                Sacc[(row + 8) * 33 + col]     = acc[mt][2];
                Sacc[(row + 8) * 33 + col + 1] = acc[mt][3];
            }
        }
        __syncthreads();

        if (tid < 64) {
            int b = tid;
            float hn[8];
            #pragma unroll
            for (int j = 0; j < 8; j++) {
                float r  = sigf(xr[j] + Sacc[b * 33 + j]);
                float z  = sigf(xi[j] + Sacc[b * 33 + 8 + j]);
                float nn = tanhf_(xn[j] + r * Sacc[b * 33 + 16 + j]);
                hn[j] = (1.0f - z) * nn + z * hown[b * 8 + j];
                hown[b * 8 + j] = hn[j];
            }
            float4 o0 = make_float4(hn[0], hn[1], hn[2], hn[3]);
            float4 o1 = make_float4(hn[4], hn[5], hn[6], hn[7]);
            float* orow = out + (size_t)(b * Tz + t) * Hz + c * 8;
            *(float4*)orow = o0;
            *(float4*)(orow + 4) = o1;
            if (write_last && t == Tz - 1) {
                float* lrow = out + (size_t)BTz * Hz + (size_t)b * Hz + c * 8;
                *(float4*)lrow = o0;
                *(float4*)(lrow + 4) = o1;
            }
            uint4 hi, lo;
            cvt8(o0, o1, hi, lo);
            __stcg((uint4*)(g_hhi[nxt] + (size_t)b * Hz + c * 8), hi);
            __stcg((uint4*)(g_hlo[nxt] + (size_t)b * Hz + c * 8), lo);
        }
        grid_sync_t(t, c);
    }
}

// ---------------- launch ----------------
extern "C" void kernel_launch(void* const* d_in, const int* in_sizes, int n_in,
                              void* d_out, int out_size) {
    const float* x   = (const float*)d_in[0];
    const float* Wir = (const float*)d_in[1];
    const float* Wii = (const float*)d_in[2];
    const float* Win = (const float*)d_in[3];
    const float* bir = (const float*)d_in[4];
    const float* bii = (const float*)d_in[5];
    const float* bin = (const float*)d_in[6];
    const float* Whr = (const float*)d_in[7];
    const float* Whi = (const float*)d_in[8];
    const float* Whn = (const float*)d_in[9];
    float* out = (float*)d_out;

    int write_last = (out_size >= BTz * Hz + Bz * Hz) ? 1 : 0;

    cudaFuncSetAttribute(xproj, cudaFuncAttributeMaxDynamicSharedMemorySize, XSM);
    cudaFuncSetAttribute(gru,   cudaFuncAttributeMaxDynamicSharedMemorySize, GSM);

    init_h<<<(Bz * Hz + 255) / 256, 256>>>();
    cvt_x<<<(int)(((size_t)BTz * INz / 8 + 255) / 256), 256>>>(x);
    cvt_w<<<(G3z * INz / 8 + 255) / 256, 256>>>(Wir, Wii, Win, bir, bii, bin);

    dim3 g1(BTz / 128, G3z / 64);
    xproj<<<g1, 256, XSM>>>();

    gru<<<NCTA, 256, GSM>>>(Whr, Whi, Whn, out, write_last);
}